// round 3
// baseline (speedup 1.0000x reference)
#include <cuda_runtime.h>

#define NB 8
#define NX 128
#define NY 128
#define NW 24
#define ND 4
#define NTS 8
#define NKY 65

// scratch (allocation-free)
__device__ float4 g_h [(NB*NX*NY*NW)/4];     // h (B,X,Y,W)
__device__ float4 g_Hy[NB*NX*NKY*(NW/2)];    // rfft-y(h): [b*x][ky][c] -> (A.re,A.im,B.re,B.im)
__device__ float4 g_Yx[NB*NX*NKY*(NW/2)];    // post spectral-conv + inv-x-FFT
__device__ float4 g_W2[(ND*NX*NKY*NW*NW)/2]; // [l][p=bitrev(kx)][ky][i*24+o] float2, scaled 1/16384

__device__ __forceinline__ float2 cmul(float2 a, float2 b){
    return make_float2(fmaf(a.x,b.x,-a.y*b.y), fmaf(a.x,b.y,a.y*b.x));
}
__device__ __forceinline__ float2 cmulc(float2 a, float2 b){ // a*conj(b)
    return make_float2(fmaf(a.x,b.x, a.y*b.y), fmaf(a.y,b.x,-a.x*b.y));
}

// DIF: natural -> bit-reversed, tw[k]=exp(-2pi i k/128)
template<int NF,int NTH>
__device__ __forceinline__ void dif128(float2* z, const float2* tw, int tid){
    #pragma unroll
    for (int s=6; s>=0; --s){
        __syncthreads();
        const int span = 1<<s;
        for (int idx=tid; idx<NF*64; idx+=NTH){
            int f=idx%NF, r=idx/NF;
            int j=r&(span-1);
            int i0=((r>>s)<<(s+1))+j;
            float2* row=z+f*129;
            float2 a=row[i0], b=row[i0+span];
            row[i0]=make_float2(a.x+b.x,a.y+b.y);
            float2 d=make_float2(a.x-b.x,a.y-b.y);
            row[i0+span]=cmul(d,tw[j<<(6-s)]);
        }
    }
    __syncthreads();
}
// inverse DIT: bit-reversed -> natural, unscaled
template<int NF,int NTH>
__device__ __forceinline__ void dit128i(float2* z, const float2* tw, int tid){
    #pragma unroll
    for (int s=0; s<=6; ++s){
        __syncthreads();
        const int span = 1<<s;
        for (int idx=tid; idx<NF*64; idx+=NTH){
            int f=idx%NF, r=idx/NF;
            int j=r&(span-1);
            int i0=((r>>s)<<(s+1))+j;
            float2* row=z+f*129;
            float2 a=row[i0];
            float2 b=cmulc(row[i0+span],tw[j<<(6-s)]);
            row[i0]     =make_float2(a.x+b.x,a.y+b.y);
            row[i0+span]=make_float2(a.x-b.x,a.y-b.y);
        }
    }
    __syncthreads();
}
template<int NF,int NTH>
__device__ __forceinline__ void brevperm(float2* z, int tid){
    for (int idx=tid; idx<NF*128; idx+=NTH){
        int f=idx%NF, p=idx/NF;
        int q=(int)(__brev((unsigned)p)>>25);
        if (p<q){ float2* row=z+f*129; float2 t=row[p]; row[p]=row[q]; row[q]=t; }
    }
    __syncthreads();
}

// forward y-rfft of real (128,24) tile (row stride 25) via channel pairing -> g_Hy
template<int NTH>
__device__ __forceinline__ void rfft_y_store(const float* hb, float2* z, const float2* tw,
                                             float4* Hy, int bx, int tid){
    for (int m=tid; m<12*128; m+=NTH){
        int c=m%12, y=m/12;
        z[c*129+y]=make_float2(hb[y*25+2*c],hb[y*25+2*c+1]);
    }
    dif128<12,NTH>(z,tw,tid);
    brevperm<12,NTH>(z,tid);
    for (int m=tid; m<12*NKY; m+=NTH){
        int c=m%12, k=m/12;
        float2 P =z[c*129+k];
        float2 Zm=z[c*129+((128-k)&127)];
        float2 A=make_float2(0.5f*(P.x+Zm.x),0.5f*(P.y-Zm.y));
        float2 B=make_float2(0.5f*(P.y+Zm.y),0.5f*(Zm.x-P.x));
        Hy[(size_t)(bx*NKY+k)*12+c]=make_float4(A.x,A.y,B.x,B.y);
    }
}

// weight transpose + bitrev + scale
__global__ void k_wt(const float* __restrict__ spec){
    __shared__ float2 tile[64*67];
    const int kx=blockIdx.x, l=blockIdx.y;
    const int p=(int)(__brev((unsigned)kx)>>25);
    const float sc=1.0f/16384.0f;
    const float2* s2=(const float2*)spec;
    float2* w2=(float2*)g_W2;
    for (int ch=0; ch<9; ch++){
        int io0=ch*64;
        for (int e=threadIdx.x; e<64*65; e+=blockDim.x){
            int iol=e/65, ky=e%65, io=io0+iol;
            int i=io/24, o=io%24;
            float2 v=s2[(((size_t)(l*NW+i)*NW+o)*NX+kx)*NKY+ky];
            tile[iol*67+ky]=make_float2(v.x*sc,v.y*sc);
        }
        __syncthreads();
        for (int e=threadIdx.x; e<64*65; e+=blockDim.x){
            int iol=e%64, ky=e/64;
            w2[(((size_t)(l*NX+p)*NKY+ky)*576)+io0+iol]=tile[iol*67+ky];
        }
        __syncthreads();
    }
}

// h0 = x @ in_w + in_b
__global__ void k_in(const float* __restrict__ x, const float* __restrict__ iw,
                     const float* __restrict__ ib){
    int t=blockIdx.x*blockDim.x+threadIdx.x;
    if (t>=NB*NX*NY*NW) return;
    int w=t%NW, s=t/NW;
    ((float*)g_h)[t]=fmaf(x[s*2],iw[w],fmaf(x[s*2+1],iw[NW+w],ib[w]));
}

// initial forward y-rfft
__global__ void k_f1(){
    __shared__ float  hb[128*25];
    __shared__ float2 z[12*129];
    __shared__ float2 tw[64];
    int tid=threadIdx.x, bx=blockIdx.x;
    if (tid<64){ float s,c; sincospif(-(float)tid/64.0f,&s,&c); tw[tid]=make_float2(c,s); }
    const float* hs=((const float*)g_h)+(size_t)bx*128*24;
    for (int m=tid; m<128*24; m+=256) hb[(m/24)*25+m%24]=hs[m];
    __syncthreads();
    rfft_y_store<256>(hb,z,tw,g_Hy,bx,tid);
}

// S2: fwd x-FFT -> spectral matmul -> inv x-FFT. block=(ky, bgroup of 4 batches), 384 thr
__global__ void k_s2(int layer){
    extern __shared__ float2 sm[];
    float2* z=sm;
    float2* tw=sm+96*129;
    const int ky=blockIdx.x, bg=blockIdx.y, tid=threadIdx.x;
    if (tid<64){ float s,c; sincospif(-(float)tid/64.0f,&s,&c); tw[tid]=make_float2(c,s); }
    const float2* Hy=(const float2*)g_Hy;
    float2* Yx=(float2*)g_Yx;
    const float2* w2l=((const float2*)g_W2)+(size_t)layer*NX*NKY*576;

    for (int m=tid; m<4*128*24; m+=384){
        int w=m%24, x=(m/24)&127, b4=m/(24*128);
        z[(b4*24+w)*129+x]=Hy[((size_t)((bg*4+b4)*128+x)*NKY+ky)*24+w];
    }
    dif128<96,384>(z,tw,tid);   // z[row][p] = Hf[kx=bitrev(p)]

    const int o=tid%24, b4=(tid/24)&3, ps=tid/96;
    for (int pc=0; pc<32; pc++){
        int p=pc*4+ps;
        const float2* wrow=w2l+((size_t)p*NKY+ky)*576+o;
        float2 acc=make_float2(0.f,0.f);
        #pragma unroll
        for (int i=0; i<24; i++){
            float2 hv=z[(b4*24+i)*129+p];
            float2 wv=__ldg(wrow+i*24);
            acc.x=fmaf(hv.x,wv.x,acc.x);
            acc.x=fmaf(-hv.y,wv.y,acc.x);
            acc.y=fmaf(hv.x,wv.y,acc.y);
            acc.y=fmaf(hv.y,wv.x,acc.y);
        }
        __syncthreads();
        z[(b4*24+o)*129+p]=acc;
    }
    dit128i<96,384>(z,tw,tid);

    for (int m=tid; m<4*128*24; m+=384){
        int w=m%24, x=(m/24)&127, b4=m/(24*128);
        Yx[((size_t)((bg*4+b4)*128+x)*NKY+ky)*24+w]=z[(b4*24+w)*129+x];
    }
}

// S3: inv y-rfft + relu + 1x1 conv (+ out proj) + fwd y-rfft of h_new
__global__ void k_s3(const float* __restrict__ cw, const float* __restrict__ cb,
                     const float* __restrict__ ow, const float* __restrict__ ob,
                     float* __restrict__ out, int t, int last_layer){
    __shared__ float  hb[128*25];
    __shared__ float  x1[128*25];
    __shared__ float2 z[12*129];
    __shared__ float2 tw[64];
    __shared__ float  scw[576];
    __shared__ float  scb[24];
    __shared__ float  sow[24];
    const int tid=threadIdx.x, bx=blockIdx.x;
    if (tid<64){ float s,c; sincospif(-(float)tid/64.0f,&s,&c); tw[tid]=make_float2(c,s); }
    for (int m=tid; m<576; m+=256) scw[m]=cw[m];
    if (tid<24){ scb[tid]=cb[tid]; sow[tid]=ow[tid]; }

    // rebuild packed spectrum Z = A + iB (imag of DC/Nyquist bins dropped, numpy irfft semantics)
    const float4* Yx=(const float4*)g_Yx;
    for (int m=tid; m<12*128; m+=256){
        int c=m%12, k=m/12;
        float2 Zv;
        if (k<=64){
            float4 v=Yx[(size_t)(bx*NKY+k)*12+c];
            if (k==0||k==64) Zv=make_float2(v.x,v.z);
            else             Zv=make_float2(v.x-v.w,v.y+v.z);
        } else {
            float4 v=Yx[(size_t)(bx*NKY+(128-k))*12+c];
            Zv=make_float2(v.x+v.w,v.z-v.y);
        }
        z[c*129+k]=Zv;
    }
    float* hg=((float*)g_h)+(size_t)bx*128*24;
    for (int m=tid; m<128*24; m+=256) hb[(m/24)*25+m%24]=hg[m];
    __syncthreads();

    brevperm<12,256>(z,tid);
    dit128i<12,256>(z,tw,tid);

    for (int m=tid; m<12*128; m+=256){
        int c=m%12, y=m/12;
        float2 v=z[c*129+y];
        x1[y*25+2*c]  =v.x;
        x1[y*25+2*c+1]=v.y;
    }
    __syncthreads();

    // h_new = relu(x1) + h @ conv_w + conv_b
    for (int m=tid; m<128*24; m+=256){
        int o=m%24, y=m/24;
        float acc=scb[o];
        #pragma unroll
        for (int i=0; i<24; i++) acc=fmaf(hb[y*25+i],scw[i*24+o],acc);
        x1[y*25+o]=fmaxf(x1[y*25+o],0.0f)+acc;
    }
    __syncthreads();

    for (int m=tid; m<128*24; m+=256) hg[m]=x1[(m/24)*25+m%24];

    if (last_layer){
        int b=bx>>7, x=bx&127;
        float obias=ob[0];
        float* od=out+(((size_t)(b*NTS+t)*128+x)*128);
        for (int y=tid; y<128; y+=256){
            float acc=obias;
            #pragma unroll
            for (int w=0; w<24; w++) acc=fmaf(x1[y*25+w],sow[w],acc);
            od[y]=acc;
        }
    }
    rfft_y_store<256>(x1,z,tw,g_Hy,bx,tid);
}

extern "C" void kernel_launch(void* const* d_in, const int* in_sizes, int n_in,
                              void* d_out, int out_size){
    const float* x    =(const float*)d_in[0];
    const float* in_w =(const float*)d_in[1];
    const float* in_b =(const float*)d_in[2];
    const float* spec =(const float*)d_in[3];
    const float* cw   =(const float*)d_in[4];
    const float* cb   =(const float*)d_in[5];
    const float* ow   =(const float*)d_in[6];
    const float* ob   =(const float*)d_in[7];
    float* out=(float*)d_out;

    cudaFuncSetAttribute(k_s2, cudaFuncAttributeMaxDynamicSharedMemorySize, 99584);

    k_wt<<<dim3(128,4),256>>>(spec);
    k_in<<<(NB*NX*NY*NW+255)/256,256>>>(x,in_w,in_b);
    k_f1<<<NB*NX,256>>>();
    for (int t=0; t<NTS; t++){
        for (int l=0; l<ND; l++){
            k_s2<<<dim3(NKY,2),384,99584>>>(l);
            k_s3<<<NB*NX,256>>>(cw+l*576,cb+l*24,ow,ob,out,t,l==ND-1);
        }
    }
}

// round 4
// speedup vs baseline: 1.3034x; 1.3034x over previous
#include <cuda_runtime.h>

#define NB 8
#define NX 128
#define NY 128
#define NW 24
#define ND 4
#define NTS 8
#define NKY 65

// scratch (allocation-free)
__device__ float4 g_h [(NB*NX*NY*NW)/4];     // h (B,X,Y,W)
__device__ float4 g_Hy[NB*NX*NKY*(NW/2)];    // rfft-y(h): [b*x][ky][c] -> (A.re,A.im,B.re,B.im)
__device__ float4 g_Yx[NB*NX*NKY*(NW/2)];    // post spectral-conv + inv-x-FFT
__device__ float4 g_W2[(ND*NX*NKY*NW*NW)/2]; // [l][p=bitrev(kx)][ky][i*24+o] float2, scaled 1/16384

__device__ __forceinline__ float2 cmul(float2 a, float2 b){
    return make_float2(fmaf(a.x,b.x,-a.y*b.y), fmaf(a.x,b.y,a.y*b.x));
}
__device__ __forceinline__ float2 cmulc(float2 a, float2 b){ // a*conj(b)
    return make_float2(fmaf(a.x,b.x, a.y*b.y), fmaf(a.y,b.x,-a.x*b.y));
}
__device__ __forceinline__ int rb7(int k){ return (int)(__brev((unsigned)k)>>25); }

// DIF: natural -> bit-reversed, tw[k]=exp(-2pi i k/128)
template<int NF,int NTH>
__device__ __forceinline__ void dif128(float2* z, const float2* tw, int tid){
    #pragma unroll
    for (int s=6; s>=0; --s){
        __syncthreads();
        const int span = 1<<s;
        for (int idx=tid; idx<NF*64; idx+=NTH){
            int f=idx%NF, r=idx/NF;
            int j=r&(span-1);
            int i0=((r>>s)<<(s+1))+j;
            float2* row=z+f*129;
            float2 a=row[i0], b=row[i0+span];
            row[i0]=make_float2(a.x+b.x,a.y+b.y);
            float2 d=make_float2(a.x-b.x,a.y-b.y);
            row[i0+span]=cmul(d,tw[j<<(6-s)]);
        }
    }
    __syncthreads();
}
// inverse DIT: bit-reversed -> natural, unscaled
template<int NF,int NTH>
__device__ __forceinline__ void dit128i(float2* z, const float2* tw, int tid){
    #pragma unroll
    for (int s=0; s<=6; ++s){
        __syncthreads();
        const int span = 1<<s;
        for (int idx=tid; idx<NF*64; idx+=NTH){
            int f=idx%NF, r=idx/NF;
            int j=r&(span-1);
            int i0=((r>>s)<<(s+1))+j;
            float2* row=z+f*129;
            float2 a=row[i0];
            float2 b=cmulc(row[i0+span],tw[j<<(6-s)]);
            row[i0]     =make_float2(a.x+b.x,a.y+b.y);
            row[i0+span]=make_float2(a.x-b.x,a.y-b.y);
        }
    }
    __syncthreads();
}

// forward y-rfft of real (128,24) tile (row stride 25) via channel pairing -> g_Hy
// dif output is bit-reversed; we index it directly with rb7 (no permute pass).
template<int NTH>
__device__ __forceinline__ void rfft_y_store(const float* hb, float2* z, const float2* tw,
                                             float4* Hy, int bx, int tid){
    for (int m=tid; m<12*128; m+=NTH){
        int c=m%12, y=m/12;
        z[c*129+y]=make_float2(hb[y*25+2*c],hb[y*25+2*c+1]);
    }
    dif128<12,NTH>(z,tw,tid);
    for (int m=tid; m<12*NKY; m+=NTH){
        int c=m%12, k=m/12;
        float2 P =z[c*129+rb7(k)];
        float2 Zm=z[c*129+rb7((128-k)&127)];
        float2 A=make_float2(0.5f*(P.x+Zm.x),0.5f*(P.y-Zm.y));
        float2 B=make_float2(0.5f*(P.y+Zm.y),0.5f*(Zm.x-P.x));
        Hy[(size_t)(bx*NKY+k)*12+c]=make_float4(A.x,A.y,B.x,B.y);
    }
}

// weight transpose + bitrev + scale
__global__ void k_wt(const float* __restrict__ spec){
    __shared__ float2 tile[64*67];
    const int kx=blockIdx.x, l=blockIdx.y;
    const int p=rb7(kx);
    const float sc=1.0f/16384.0f;
    const float2* s2=(const float2*)spec;
    float2* w2=(float2*)g_W2;
    for (int ch=0; ch<9; ch++){
        int io0=ch*64;
        for (int e=threadIdx.x; e<64*65; e+=blockDim.x){
            int iol=e/65, ky=e%65, io=io0+iol;
            int i=io/24, o=io%24;
            float2 v=s2[(((size_t)(l*NW+i)*NW+o)*NX+kx)*NKY+ky];
            tile[iol*67+ky]=make_float2(v.x*sc,v.y*sc);
        }
        __syncthreads();
        for (int e=threadIdx.x; e<64*65; e+=blockDim.x){
            int iol=e%64, ky=e/64;
            w2[(((size_t)(l*NX+p)*NKY+ky)*576)+io0+iol]=tile[iol*67+ky];
        }
        __syncthreads();
    }
}

// fused: h0 = x @ in_w + in_b, then forward y-rfft. one block per (b,x)
__global__ void k_f1(const float* __restrict__ x, const float* __restrict__ iw,
                     const float* __restrict__ ib){
    __shared__ float  hb[128*25];
    __shared__ float2 z[12*129];
    __shared__ float2 tw[64];
    __shared__ float  siw[48];
    __shared__ float  sib[24];
    int tid=threadIdx.x, bx=blockIdx.x;
    if (tid<64){ float s,c; sincospif(-(float)tid/64.0f,&s,&c); tw[tid]=make_float2(c,s); }
    if (tid<48) siw[tid]=iw[tid];
    if (tid<24) sib[tid]=ib[tid];
    __syncthreads();
    const float* xp = x + (size_t)bx*128*2;
    float* hg = ((float*)g_h) + (size_t)bx*128*24;
    for (int m=tid; m<128*24; m+=256){
        int w=m%24, y=m/24;
        float v=fmaf(xp[2*y],siw[w],fmaf(xp[2*y+1],siw[24+w],sib[w]));
        hb[y*25+w]=v;
        hg[y*24+w]=v;
    }
    __syncthreads();
    rfft_y_store<256>(hb,z,tw,g_Hy,bx,tid);
}

// S2: fwd x-FFT -> spectral matmul (barrier-free, double buffer) -> inv x-FFT
// block = (ky, bgroup of 2 batches), 384 threads, smem 99584B
__global__ void k_s2(int layer){
    extern __shared__ float2 sm[];
    float2* z =sm;               // 48*129
    float2* zo=sm+48*129;        // 48*129
    float2* tw=sm+2*48*129;      // 64
    const int ky=blockIdx.x, bg=blockIdx.y, tid=threadIdx.x;
    if (tid<64){ float s,c; sincospif(-(float)tid/64.0f,&s,&c); tw[tid]=make_float2(c,s); }
    const float2* Hy=(const float2*)g_Hy;
    float2* Yx=(float2*)g_Yx;
    const float2* w2l=((const float2*)g_W2)+(size_t)layer*NX*NKY*576;

    for (int m=tid; m<2*128*24; m+=384){
        int w=m%24, x=(m/24)&127, b2=m/(24*128);
        z[(b2*24+w)*129+x]=Hy[((size_t)((bg*2+b2)*128+x)*NKY+ky)*24+w];
    }
    dif128<48,384>(z,tw,tid);   // z[row][p] = Hf[kx=rb7(p)]

    // barrier-free spectral matmul: read z, write zo
    const int o=tid%24, b2=(tid/24)&1, ps=tid/48;   // ps in 0..7
    #pragma unroll 2
    for (int pc=0; pc<16; pc++){
        int p=pc*8+ps;
        const float2* wrow=w2l+((size_t)p*NKY+ky)*576+o;
        float2 acc=make_float2(0.f,0.f);
        #pragma unroll
        for (int i=0; i<24; i++){
            float2 hv=z[(b2*24+i)*129+p];
            float2 wv=__ldg(wrow+i*24);
            acc.x=fmaf(hv.x,wv.x,acc.x);
            acc.x=fmaf(-hv.y,wv.y,acc.x);
            acc.y=fmaf(hv.x,wv.y,acc.y);
            acc.y=fmaf(hv.y,wv.x,acc.y);
        }
        zo[(b2*24+o)*129+p]=acc;
    }
    dit128i<48,384>(zo,tw,tid);  // leading sync makes zo writes visible

    for (int m=tid; m<2*128*24; m+=384){
        int w=m%24, x=(m/24)&127, b2=m/(24*128);
        Yx[((size_t)((bg*2+b2)*128+x)*NKY+ky)*24+w]=zo[(b2*24+w)*129+x];
    }
}

// S3: inv y-rfft + relu + 1x1 conv (+ out proj) + fwd y-rfft of h_new
__global__ void k_s3(const float* __restrict__ cw, const float* __restrict__ cb,
                     const float* __restrict__ ow, const float* __restrict__ ob,
                     float* __restrict__ out, int t, int last_layer){
    __shared__ float  hb[128*25];
    __shared__ float  x1[128*25];
    __shared__ float2 z[12*129];
    __shared__ float2 tw[64];
    __shared__ float  scw[576];
    __shared__ float  scb[24];
    __shared__ float  sow[24];
    const int tid=threadIdx.x, bx=blockIdx.x;
    if (tid<64){ float s,c; sincospif(-(float)tid/64.0f,&s,&c); tw[tid]=make_float2(c,s); }
    for (int m=tid; m<576; m+=256) scw[m]=cw[m];
    if (tid<24){ scb[tid]=cb[tid]; sow[tid]=ow[tid]; }

    // rebuild packed spectrum Z = A + iB directly into BIT-REVERSED slots
    // (imag of DC/Nyquist dropped, numpy irfft semantics)
    const float4* Yx=(const float4*)g_Yx;
    for (int m=tid; m<12*128; m+=256){
        int c=m%12, k=m/12;
        float2 Zv;
        if (k<=64){
            float4 v=Yx[(size_t)(bx*NKY+k)*12+c];
            if (k==0||k==64) Zv=make_float2(v.x,v.z);
            else             Zv=make_float2(v.x-v.w,v.y+v.z);
        } else {
            float4 v=Yx[(size_t)(bx*NKY+(128-k))*12+c];
            Zv=make_float2(v.x+v.w,v.z-v.y);
        }
        z[c*129+rb7(k)]=Zv;
    }
    float* hg=((float*)g_h)+(size_t)bx*128*24;
    for (int m=tid; m<128*24; m+=256) hb[(m/24)*25+m%24]=hg[m];

    dit128i<12,256>(z,tw,tid);   // leading sync covers z/hb/scw writes

    for (int m=tid; m<12*128; m+=256){
        int c=m%12, y=m/12;
        float2 v=z[c*129+y];
        x1[y*25+2*c]  =v.x;
        x1[y*25+2*c+1]=v.y;
    }
    __syncthreads();

    // h_new = relu(x1) + h @ conv_w + conv_b
    for (int m=tid; m<128*24; m+=256){
        int o=m%24, y=m/24;
        float acc=scb[o];
        #pragma unroll
        for (int i=0; i<24; i++) acc=fmaf(hb[y*25+i],scw[i*24+o],acc);
        x1[y*25+o]=fmaxf(x1[y*25+o],0.0f)+acc;
    }
    __syncthreads();

    for (int m=tid; m<128*24; m+=256) hg[m]=x1[(m/24)*25+m%24];

    if (last_layer){
        int b=bx>>7, x=bx&127;
        float obias=ob[0];
        float* od=out+(((size_t)(b*NTS+t)*128+x)*128);
        for (int y=tid; y<128; y+=256){
            float acc=obias;
            #pragma unroll
            for (int w=0; w<24; w++) acc=fmaf(x1[y*25+w],sow[w],acc);
            od[y]=acc;
        }
    }
    rfft_y_store<256>(x1,z,tw,g_Hy,bx,tid);
}

extern "C" void kernel_launch(void* const* d_in, const int* in_sizes, int n_in,
                              void* d_out, int out_size){
    const float* x    =(const float*)d_in[0];
    const float* in_w =(const float*)d_in[1];
    const float* in_b =(const float*)d_in[2];
    const float* spec =(const float*)d_in[3];
    const float* cw   =(const float*)d_in[4];
    const float* cb   =(const float*)d_in[5];
    const float* ow   =(const float*)d_in[6];
    const float* ob   =(const float*)d_in[7];
    float* out=(float*)d_out;

    cudaFuncSetAttribute(k_s2, cudaFuncAttributeMaxDynamicSharedMemorySize, 99584);

    k_wt<<<dim3(128,4),256>>>(spec);
    k_f1<<<NB*NX,256>>>(x,in_w,in_b);
    for (int t=0; t<NTS; t++){
        for (int l=0; l<ND; l++){
            k_s2<<<dim3(NKY,4),384,99584>>>(l);
            k_s3<<<NB*NX,256>>>(cw+l*576,cb+l*24,ow,ob,out,t,l==ND-1);
        }
    }
}

// round 5
// speedup vs baseline: 2.1531x; 1.6518x over previous
#include <cuda_runtime.h>

#define NB 8
#define NX 128
#define NY 128
#define NW 24
#define ND 4
#define NTS 8
#define NKY 65
#define ZS 130   // float2 row stride (even -> float4-able, padded vs 128)

// scratch (allocation-free)
__device__ float4 g_h [(NB*NX*NY*NW)/4];     // h (B,X,Y,W)
__device__ float4 g_Hy[NB*NX*NKY*(NW/2)];    // rfft-y(h): [b*x][ky][c] -> (A.re,A.im,B.re,B.im)
__device__ float4 g_Yx[NB*NX*NKY*(NW/2)];    // post spectral-conv + inv-x-FFT
__device__ float4 g_W2[(ND*NX*NKY*NW*NW)/2]; // [l][p=bitrev(kx)][ky][i*24+o] float2, scaled 1/16384

__device__ __forceinline__ float2 cadd(float2 a, float2 b){ return make_float2(a.x+b.x,a.y+b.y); }
__device__ __forceinline__ float2 csub(float2 a, float2 b){ return make_float2(a.x-b.x,a.y-b.y); }
__device__ __forceinline__ float2 cmul(float2 a, float2 b){
    return make_float2(fmaf(a.x,b.x,-a.y*b.y), fmaf(a.x,b.y,a.y*b.x));
}
__device__ __forceinline__ float2 cmulc(float2 a, float2 b){ // a*conj(b)
    return make_float2(fmaf(a.x,b.x, a.y*b.y), fmaf(a.y,b.x,-a.x*b.y));
}
__device__ __forceinline__ int rb7(int k){ return (int)(__brev((unsigned)k)>>25); }

// ---- radix-2^2 / radix-8 passes. Op-identical to serial radix-2 stages. ----
// DIF double stage (S, S-1): quads {i0, i0+H2, i0+H, i0+H+H2}
template<int NF,int NTH,int S>
__device__ __forceinline__ void dif_q(float2* z, const float2* tw, int tid){
    __syncthreads();
    const int H=1<<S, H2=H>>1;
    for (int idx=tid; idx<NF*32; idx+=NTH){
        int f=idx>>5, r=idx&31;
        int j=r&(H2-1), g=r>>(S-1);
        int i0=(g<<(S+1))+j;
        float2* row=z+f*ZS;
        float2 a=row[i0], b=row[i0+H2], c=row[i0+H], d=row[i0+H+H2];
        float2 a1=cadd(a,c), c1=cmul(csub(a,c),tw[j<<(6-S)]);
        float2 b1=cadd(b,d), d1=cmul(csub(b,d),tw[(j+H2)<<(6-S)]);
        float2 t3=tw[j<<(7-S)];
        row[i0]      =cadd(a1,b1);
        row[i0+H2]   =cmul(csub(a1,b1),t3);
        row[i0+H]    =cadd(c1,d1);
        row[i0+H+H2] =cmul(csub(c1,d1),t3);
    }
}
// DIF octet: stages 2,1,0 on 8 consecutive elements
template<int NF,int NTH>
__device__ __forceinline__ void dif_oct(float2* z, const float2* tw, int tid){
    __syncthreads();
    for (int idx=tid; idx<NF*16; idx+=NTH){
        int f=idx>>4, oc=idx&15;
        float4* r4=(float4*)(z+f*ZS);
        float2 e[8];
        #pragma unroll
        for (int q=0;q<4;q++){ float4 v=r4[oc*4+q]; e[2*q]=make_float2(v.x,v.y); e[2*q+1]=make_float2(v.z,v.w); }
        #pragma unroll
        for (int st=2; st>=0; --st){
            int h=1<<st;
            #pragma unroll
            for (int k=0;k<8;k++) if(!(k&h)){
                float2 a=e[k], b=e[k+h];
                e[k]=cadd(a,b);
                e[k+h]=cmul(csub(a,b),tw[(k&(h-1))<<(6-st)]);
            }
        }
        #pragma unroll
        for (int q=0;q<4;q++) r4[oc*4+q]=make_float4(e[2*q].x,e[2*q].y,e[2*q+1].x,e[2*q+1].y);
    }
}
// DIT octet: stages 0,1,2 (conj twiddles)
template<int NF,int NTH>
__device__ __forceinline__ void dit_oct(float2* z, const float2* tw, int tid){
    __syncthreads();
    for (int idx=tid; idx<NF*16; idx+=NTH){
        int f=idx>>4, oc=idx&15;
        float4* r4=(float4*)(z+f*ZS);
        float2 e[8];
        #pragma unroll
        for (int q=0;q<4;q++){ float4 v=r4[oc*4+q]; e[2*q]=make_float2(v.x,v.y); e[2*q+1]=make_float2(v.z,v.w); }
        #pragma unroll
        for (int st=0; st<3; ++st){
            int h=1<<st;
            #pragma unroll
            for (int k=0;k<8;k++) if(!(k&h)){
                float2 a=e[k], b=cmulc(e[k+h],tw[(k&(h-1))<<(6-st)]);
                e[k]=cadd(a,b);
                e[k+h]=csub(a,b);
            }
        }
        #pragma unroll
        for (int q=0;q<4;q++) r4[oc*4+q]=make_float4(e[2*q].x,e[2*q].y,e[2*q+1].x,e[2*q+1].y);
    }
}
// DIT double stage (S, S+1): quads {i0, i0+H, i0+2H, i0+3H}
template<int NF,int NTH,int S>
__device__ __forceinline__ void dit_q(float2* z, const float2* tw, int tid){
    __syncthreads();
    const int H=1<<S;
    for (int idx=tid; idx<NF*32; idx+=NTH){
        int f=idx>>5, r=idx&31;
        int j=r&(H-1), g=r>>S;
        int i0=(g<<(S+2))+j;
        float2* row=z+f*ZS;
        float2 a=row[i0], b=row[i0+H], c=row[i0+2*H], d=row[i0+3*H];
        float2 w=tw[j<<(6-S)];
        float2 bb=cmulc(b,w), dd=cmulc(d,w);
        float2 a1=cadd(a,bb), b1=csub(a,bb);
        float2 c1=cadd(c,dd), d1=csub(c,dd);
        float2 cw=cmulc(c1,tw[j<<(5-S)]);
        float2 dw=cmulc(d1,tw[(j+H)<<(5-S)]);
        row[i0]    =cadd(a1,cw);
        row[i0+2*H]=csub(a1,cw);
        row[i0+H]  =cadd(b1,dw);
        row[i0+3*H]=csub(b1,dw);
    }
}

// forward y-FFT of packed z (12 rows x 128) + rfft extract -> g_Hy
template<int NTH>
__device__ __forceinline__ void rfft_store(float2* z, const float2* tw, float4* Hy, int bx, int tid){
    dif_q<12,NTH,6>(z,tw,tid);
    dif_q<12,NTH,4>(z,tw,tid);
    dif_oct<12,NTH>(z,tw,tid);
    __syncthreads();
    for (int m=tid; m<12*NKY; m+=NTH){
        int c=m%12, k=m/12;
        float2 P =z[c*ZS+rb7(k)];
        float2 Zm=z[c*ZS+rb7((128-k)&127)];
        float2 A=make_float2(0.5f*(P.x+Zm.x),0.5f*(P.y-Zm.y));
        float2 B=make_float2(0.5f*(P.y+Zm.y),0.5f*(Zm.x-P.x));
        Hy[(size_t)(bx*NKY+k)*12+c]=make_float4(A.x,A.y,B.x,B.y);
    }
}

// weight transpose + bitrev + scale
__global__ void k_wt(const float* __restrict__ spec){
    __shared__ float2 tile[64*67];
    const int kx=blockIdx.x, l=blockIdx.y;
    const int p=rb7(kx);
    const float sc=1.0f/16384.0f;
    const float2* s2=(const float2*)spec;
    float2* w2=(float2*)g_W2;
    for (int ch=0; ch<9; ch++){
        int io0=ch*64;
        for (int e=threadIdx.x; e<64*65; e+=blockDim.x){
            int iol=e/65, ky=e%65, io=io0+iol;
            int i=io/24, o=io%24;
            float2 v=s2[(((size_t)(l*NW+i)*NW+o)*NX+kx)*NKY+ky];
            tile[iol*67+ky]=make_float2(v.x*sc,v.y*sc);
        }
        __syncthreads();
        for (int e=threadIdx.x; e<64*65; e+=blockDim.x){
            int iol=e%64, ky=e/64;
            w2[(((size_t)(l*NX+p)*NKY+ky)*576)+io0+iol]=tile[iol*67+ky];
        }
        __syncthreads();
    }
}

// fused: h0 = x @ in_w + in_b (packed straight into z) + forward y-rfft
__global__ void k_f1(const float* __restrict__ x, const float* __restrict__ iw,
                     const float* __restrict__ ib){
    __shared__ float2 z[12*ZS];
    __shared__ float2 tw[64];
    __shared__ float  siw[48];
    __shared__ float  sib[24];
    int tid=threadIdx.x, bx=blockIdx.x;
    if (tid<64){ float s,c; sincospif(-(float)tid/64.0f,&s,&c); tw[tid]=make_float2(c,s); }
    if (tid<48) siw[tid]=iw[tid];
    if (tid<24) sib[tid]=ib[tid];
    __syncthreads();
    const float* xp=x+(size_t)bx*128*2;
    float2* hg2=(float2*)(((float*)g_h)+(size_t)bx*128*24);
    for (int m=tid; m<12*128; m+=256){
        int c=m%12, y=m/12;
        float x0=xp[2*y], x1v=xp[2*y+1];
        float v0=fmaf(x0,siw[2*c],  fmaf(x1v,siw[24+2*c],  sib[2*c]));
        float v1=fmaf(x0,siw[2*c+1],fmaf(x1v,siw[24+2*c+1],sib[2*c+1]));
        z[c*ZS+y]=make_float2(v0,v1);
        hg2[y*12+c]=make_float2(v0,v1);
    }
    rfft_store<256>(z,tw,g_Hy,bx,tid);
}

// S2: fwd x-FFT -> spectral matmul (dual-batch accum, barrier-free) -> inv x-FFT
// block = (ky, bgroup of 2 batches), 384 threads, dyn smem 100352B
__global__ void k_s2(int layer){
    extern __shared__ float2 sm[];
    float2* z =sm;             // 48*ZS
    float2* zo=sm+48*ZS;       // 48*ZS
    float2* tw=sm+96*ZS;       // 64
    const int ky=blockIdx.x, bg=blockIdx.y, tid=threadIdx.x;
    if (tid<64){ float s,c; sincospif(-(float)tid/64.0f,&s,&c); tw[tid]=make_float2(c,s); }
    const float2* Hy=(const float2*)g_Hy;
    float2* Yx=(float2*)g_Yx;
    const float2* w2l=((const float2*)g_W2)+(size_t)layer*NX*NKY*576;

    for (int m=tid; m<2*128*24; m+=384){
        int w=m%24, x=(m/24)&127, b2=m/(24*128);
        z[(b2*24+w)*ZS+x]=Hy[((size_t)((bg*2+b2)*128+x)*NKY+ky)*24+w];
    }
    dif_q<48,384,6>(z,tw,tid);
    dif_q<48,384,4>(z,tw,tid);
    dif_oct<48,384>(z,tw,tid);
    __syncthreads();

    // spectral matmul: z[row=chan][p] -> zo, both batches per thread (weights read once)
    const int o=tid%24, pp=tid/24;   // pp in 0..15
    #pragma unroll 2
    for (int pc=0; pc<8; pc++){
        int p=pc*16+pp;
        const float2* wrow=w2l+((size_t)p*NKY+ky)*576+o;
        float2 acc0=make_float2(0.f,0.f), acc1=make_float2(0.f,0.f);
        #pragma unroll
        for (int i=0; i<24; i++){
            float2 wv=__ldg(wrow+i*24);
            float2 h0=z[i*ZS+p];
            float2 h1=z[(24+i)*ZS+p];
            acc0.x=fmaf(h0.x,wv.x,acc0.x); acc0.x=fmaf(-h0.y,wv.y,acc0.x);
            acc0.y=fmaf(h0.x,wv.y,acc0.y); acc0.y=fmaf(h0.y,wv.x,acc0.y);
            acc1.x=fmaf(h1.x,wv.x,acc1.x); acc1.x=fmaf(-h1.y,wv.y,acc1.x);
            acc1.y=fmaf(h1.x,wv.y,acc1.y); acc1.y=fmaf(h1.y,wv.x,acc1.y);
        }
        zo[o*ZS+p]=acc0;
        zo[(24+o)*ZS+p]=acc1;
    }

    dit_oct<48,384>(zo,tw,tid);     // entry sync covers matmul writes
    dit_q<48,384,3>(zo,tw,tid);
    dit_q<48,384,5>(zo,tw,tid);
    __syncthreads();

    for (int m=tid; m<2*128*24; m+=384){
        int w=m%24, x=(m/24)&127, b2=m/(24*128);
        Yx[((size_t)((bg*2+b2)*128+x)*NKY+ky)*24+w]=zo[(b2*24+w)*ZS+x];
    }
}

// S3: inv y-rfft + relu + 1x1 conv (+ out proj) + fwd y-rfft of h_new, all in one z buffer
__global__ void k_s3(const float* __restrict__ cw, const float* __restrict__ cb,
                     const float* __restrict__ ow, const float* __restrict__ ob,
                     float* __restrict__ out, int t, int last_layer){
    __shared__ float2 z[12*ZS];
    __shared__ float2 tw[64];
    __shared__ float  scw[576];
    __shared__ float  scb[24];
    __shared__ float  sow[24];
    const int tid=threadIdx.x, bx=blockIdx.x;
    if (tid<64){ float s,c; sincospif(-(float)tid/64.0f,&s,&c); tw[tid]=make_float2(c,s); }
    for (int m=tid; m<576; m+=256) scw[m]=cw[m];
    if (tid<24){ scb[tid]=cb[tid]; sow[tid]=ow[tid]; }

    // rebuild packed spectrum Z = A + iB into BIT-REVERSED slots (numpy irfft: DC/Nyq imag dropped)
    const float4* Yx=(const float4*)g_Yx;
    for (int m=tid; m<12*128; m+=256){
        int c=m%12, k=m/12;
        float2 Zv;
        if (k<=64){
            float4 v=Yx[(size_t)(bx*NKY+k)*12+c];
            if (k==0||k==64) Zv=make_float2(v.x,v.z);
            else             Zv=make_float2(v.x-v.w,v.y+v.z);
        } else {
            float4 v=Yx[(size_t)(bx*NKY+(128-k))*12+c];
            Zv=make_float2(v.x+v.w,v.z-v.y);
        }
        z[c*ZS+rb7(k)]=Zv;
    }
    dit_oct<12,256>(z,tw,tid);   // entry sync covers z/scw writes
    dit_q<12,256,3>(z,tw,tid);
    dit_q<12,256,5>(z,tw,tid);

    // conv fused with unpack+repack: thread owns (y, half) -> 12 outputs, thread-private z slots
    float* hg=((float*)g_h)+(size_t)bx*128*24;
    const int y=tid>>1, half=tid&1, c0=half*6;
    float hrow[24];
    {
        const float4* h4=(const float4*)(hg+y*24);
        #pragma unroll
        for (int q=0;q<6;q++){ float4 v=h4[q]; hrow[4*q]=v.x; hrow[4*q+1]=v.y; hrow[4*q+2]=v.z; hrow[4*q+3]=v.w; }
    }
    __syncthreads();             // all h_old reads done before any h_new write; z DIT complete
    {
        float2 zc[6];
        #pragma unroll
        for (int j=0;j<6;j++) zc[j]=z[(c0+j)*ZS+y];
        float acc[12];
        #pragma unroll
        for (int j=0;j<12;j++) acc[j]=scb[c0*2+j];
        #pragma unroll
        for (int i=0;i<24;i++){
            float hv=hrow[i];
            const float* wr=scw+i*24+c0*2;
            #pragma unroll
            for (int j=0;j<12;j++) acc[j]=fmaf(hv,wr[j],acc[j]);
        }
        float r[12];
        #pragma unroll
        for (int j=0;j<6;j++){
            r[2*j]  =fmaxf(zc[j].x,0.f)+acc[2*j];
            r[2*j+1]=fmaxf(zc[j].y,0.f)+acc[2*j+1];
        }
        #pragma unroll
        for (int j=0;j<6;j++) z[(c0+j)*ZS+y]=make_float2(r[2*j],r[2*j+1]);
        float4* h4o=(float4*)(hg+y*24+c0*2);
        #pragma unroll
        for (int q=0;q<3;q++) h4o[q]=make_float4(r[4*q],r[4*q+1],r[4*q+2],r[4*q+3]);
    }
    __syncthreads();             // packed h_new visible block-wide

    if (last_layer && tid<128){
        int b=bx>>7, xx=bx&127;
        float acc=ob[0];
        #pragma unroll
        for (int c=0;c<12;c++){
            float2 v=z[c*ZS+tid];
            acc=fmaf(v.x,sow[2*c],acc);
            acc=fmaf(v.y,sow[2*c+1],acc);
        }
        out[(((size_t)(b*NTS+t)*128+xx)*128)+tid]=acc;
    }

    rfft_store<256>(z,tw,g_Hy,bx,tid);  // entry syncs order out-proj reads before DIF writes
}

extern "C" void kernel_launch(void* const* d_in, const int* in_sizes, int n_in,
                              void* d_out, int out_size){
    const float* x    =(const float*)d_in[0];
    const float* in_w =(const float*)d_in[1];
    const float* in_b =(const float*)d_in[2];
    const float* spec =(const float*)d_in[3];
    const float* cw   =(const float*)d_in[4];
    const float* cb   =(const float*)d_in[5];
    const float* ow   =(const float*)d_in[6];
    const float* ob   =(const float*)d_in[7];
    float* out=(float*)d_out;

    cudaFuncSetAttribute(k_s2, cudaFuncAttributeMaxDynamicSharedMemorySize, 100352);

    k_wt<<<dim3(128,4),256>>>(spec);
    k_f1<<<NB*NX,256>>>(x,in_w,in_b);
    for (int t=0; t<NTS; t++){
        for (int l=0; l<ND; l++){
            k_s2<<<dim3(NKY,4),384,100352>>>(l);
            k_s3<<<NB*NX,256>>>(cw+l*576,cb+l*24,ow,ob,out,t,l==ND-1);
        }
    }
}